// round 17
// baseline (speedup 1.0000x reference)
#include <cuda_runtime.h>
#include <cuda_bf16.h>

// Bilinear grid sampler: B=16, H=256, W=256, C=64, fp32.
// U [B,H,W,C], grid [B,H,W,2], out [B,H,W,C].
// 16 threads per pixel, one float4 per thread (256B coalesced per corner).
// EIGHT adjacent pixels per thread: extends the one axis with a measured
// positive derivative (2px->4px: 99->96.3us). Compiler-scheduled pipeline
// (no __syncwarp -- ptxas keeps regs~32 by pipelining load->fma groups),
// volatile .nc loads, streaming stores, block=64 (r9/r11 granularity win).

#define BS_B 16
#define BS_H 256
#define BS_W 256
#define BS_PIX (BS_B * BS_H * BS_W)     // 1,048,576
#define NPIX 8

__device__ __forceinline__ float4 ldg_v4_volatile(const float4* p)
{
    float4 v;
    asm volatile("ld.global.nc.v4.f32 {%0,%1,%2,%3}, [%4];"
                 : "=f"(v.x), "=f"(v.y), "=f"(v.z), "=f"(v.w)
                 : "l"(p));
    return v;
}

__device__ __forceinline__ void pixel_setup(const float gx, const float gy,
                                            int b, int lane,
                                            int& ia, int& ib, int& ic, int& id,
                                            float& wa, float& wb, float& wc, float& wd)
{
    const float x = 0.5f * (gx + 1.0f) * (float)(BS_W - 1);
    const float y = 0.5f * (gy + 1.0f) * (float)(BS_H - 1);

    const int x0 = (int)floorf(x);
    const int y0 = (int)floorf(y);

    const int x0c = min(max(x0, 0), BS_W - 1);
    const int x1c = min(max(x0 + 1, 0), BS_W - 1);
    const int y0c = min(max(y0, 0), BS_H - 1);
    const int y1c = min(max(y0 + 1, 0), BS_H - 1);

    const float x0f = (float)x0c, x1f = (float)x1c;
    const float y0f = (float)y0c, y1f = (float)y1c;

    wa = (x1f - x) * (y1f - y);
    wb = (x1f - x) * (y - y0f);
    wc = (x - x0f) * (y1f - y);
    wd = (x - x0f) * (y - y0f);

    // float4 index space: [B, H, W, 16]
    const int base = b << 16;                       // b * H * W
    const int r0 = (base + (y0c << 8)) << 4;
    const int r1 = (base + (y1c << 8)) << 4;
    const int xo0 = (x0c << 4) + lane;
    const int xo1 = (x1c << 4) + lane;
    ia = r0 + xo0;
    ib = r1 + xo0;
    ic = r0 + xo1;
    id = r1 + xo1;
}

__global__ __launch_bounds__(64)
void bilinear_sampler_kernel(const float* __restrict__ U,
                             const float* __restrict__ grid,
                             float* __restrict__ out)
{
    const int t    = blockIdx.x * 64 + threadIdx.x;
    const int lane = t & 15;
    const int g    = t >> 4;                 // 0 .. BS_PIX/8 - 1
    const int pixbase = g << 3;              // 8 adjacent pixels, same batch
    const int b = pixbase >> 16;

    const float4* __restrict__ grid4 = (const float4*)grid;
    const float4* __restrict__ U4    = (const float4*)U;
    float4* __restrict__ out4        = (float4*)out;

    // 8 pixels' coords = 64 contiguous bytes = 4 x float4 (L1 broadcast)
    float gx[NPIX], gy[NPIX];
#pragma unroll
    for (int q = 0; q < 4; q++) {
        const float4 gc = __ldg(grid4 + (g << 2) + q);
        gx[q * 2]     = gc.x;  gy[q * 2]     = gc.y;
        gx[q * 2 + 1] = gc.z;  gy[q * 2 + 1] = gc.w;
    }

#pragma unroll
    for (int k = 0; k < NPIX; k++) {
        int ia, ib, ic, id;
        float wa, wb, wc, wd;
        pixel_setup(gx[k], gy[k], b, lane, ia, ib, ic, id, wa, wb, wc, wd);

        const float4 A  = ldg_v4_volatile(U4 + ia);
        const float4 Bv = ldg_v4_volatile(U4 + ib);
        const float4 Cv = ldg_v4_volatile(U4 + ic);
        const float4 D  = ldg_v4_volatile(U4 + id);

        float4 r;
        r.x = wa * A.x + wb * Bv.x + wc * Cv.x + wd * D.x;
        r.y = wa * A.y + wb * Bv.y + wc * Cv.y + wd * D.y;
        r.z = wa * A.z + wb * Bv.z + wc * Cv.z + wd * D.z;
        r.w = wa * A.w + wb * Bv.w + wc * Cv.w + wd * D.w;
        __stcs(&out4[((pixbase + k) << 4) + lane], r);   // streaming store
    }
}

extern "C" void kernel_launch(void* const* d_in, const int* in_sizes, int n_in,
                              void* d_out, int out_size)
{
    const float* U    = (const float*)d_in[0];
    const float* grid = (const float*)d_in[1];
    float* out        = (float*)d_out;

    // (BS_PIX/8) pixel-octets * 16 lanes = 2,097,152 threads
    const int block = 64;
    const int gridsz = (BS_PIX / 8 * 16) / block;   // 32768
    bilinear_sampler_kernel<<<gridsz, block>>>(U, grid, out);
}